// round 14
// baseline (speedup 1.0000x reference)
#include <cuda_runtime.h>
#include <cuda_bf16.h>
#include <cstdint>

// Problem constants
//   x: (512,1024) f32; input/output_cores: (10,10,2,2,10) f32
//   central: (1024,1024) f32; bias: (1,1024) f32; out: (512,1024) f32
#define MROWS 51200   // 512 * 10 (l0) * 10 (r)

// Scratch (device globals: allocation-free kernel_launch)
__device__ __nv_bfloat16 g_A [(size_t)MROWS * 2048];  // [Ah | Al] bf16 per row
__device__ __nv_bfloat16 g_Bt[(size_t)1024 * 2048];   // [Bh | Bl], Bt[d][c] = central[c][d]
__device__ float         g_U [(size_t)MROWS * 1024];  // U = S @ central
__device__ float         g_P [(size_t)5120 * 1024];   // per-(b,l) partials

// ========================= helpers =========================
__device__ __forceinline__ uint32_t smem_to_u32(const void* p) {
    uint32_t a;
    asm("{ .reg .u64 t; cvta.to.shared.u64 t, %1; cvt.u32.u64 %0, t; }" : "=r"(a) : "l"(p));
    return a;
}
#define CP_ASYNC16(dst, src) \
    asm volatile("cp.async.cg.shared.global [%0], [%1], 16;" :: "r"(dst), "l"(src) : "memory")
#define CP_COMMIT() asm volatile("cp.async.commit_group;" ::: "memory")
#define CP_WAIT(n)  asm volatile("cp.async.wait_group %0;" :: "n"(n) : "memory")
#define LDMATRIX_X4(r0, r1, r2, r3, addr) \
    asm volatile("ldmatrix.sync.aligned.m8n8.x4.shared.b16 {%0,%1,%2,%3}, [%4];" \
                 : "=r"(r0), "=r"(r1), "=r"(r2), "=r"(r3) : "r"(addr))
#define MMA_BF16(c0, c1, c2, c3, a0, a1, a2, a3, b0, b1) \
    asm volatile("mma.sync.aligned.m16n8k16.row.col.f32.bf16.bf16.f32 " \
                 "{%0,%1,%2,%3}, {%4,%5,%6,%7}, {%8,%9}, {%0,%1,%2,%3};" \
                 : "+f"(c0), "+f"(c1), "+f"(c2), "+f"(c3) \
                 : "r"(a0), "r"(a1), "r"(a2), "r"(a3), "r"(b0), "r"(b1))

// f32x2 helpers
__device__ __forceinline__ uint64_t f2dup(float x) {
    uint64_t r; asm("mov.b64 %0, {%1, %1};" : "=l"(r) : "f"(x)); return r;
}
__device__ __forceinline__ uint64_t fma2(uint64_t a, uint64_t b, uint64_t c) {
    uint64_t d; asm("fma.rn.f32x2 %0, %1, %2, %3;" : "=l"(d) : "l"(a), "l"(b), "l"(c)); return d;
}
__device__ __forceinline__ float2 u2f2(uint64_t u) {
    float2 f; asm("mov.b64 {%0, %1}, %2;" : "=f"(f.x), "=f"(f.y) : "l"(u)); return f;
}

// State-buffer bank swizzle: XOR quad-index bits [3:6) into [0:3).
__device__ __forceinline__ int SWZ(int w) { return w ^ ((w >> 3) & 28); }

// ========================= sweep steps (IN-PLACE + SWZ, 128 threads, 4 outputs/thread) ==========
// State: flat[(C_idx*10 + bond)*Q + q] (pre-swizzle). M: 20x20, M[(r*2+p)*20 + (d*10+s)].

#define SWEEP_FMA_CORE(M2, v0f, v1f, v2f, v3f)                     \
    do {                                                           \
        uint64_t d0 = f2dup(v0f), d1 = f2dup(v1f);                 \
        uint64_t d2 = f2dup(v2f), d3 = f2dup(v3f);                 \
        _Pragma("unroll")                                          \
        for (int b2 = 0; b2 < 10; b2 += 2) {                       \
            ulonglong2 mm = *(const ulonglong2*)((M2) + b2);       \
            acc[0][b2]     = fma2(d0, mm.x, acc[0][b2]);           \
            acc[1][b2]     = fma2(d1, mm.x, acc[1][b2]);           \
            acc[2][b2]     = fma2(d2, mm.x, acc[2][b2]);           \
            acc[3][b2]     = fma2(d3, mm.x, acc[3][b2]);           \
            acc[0][b2 + 1] = fma2(d0, mm.y, acc[0][b2 + 1]);       \
            acc[1][b2 + 1] = fma2(d1, mm.y, acc[1][b2 + 1]);       \
            acc[2][b2 + 1] = fma2(d2, mm.y, acc[2][b2 + 1]);       \
            acc[3][b2 + 1] = fma2(d3, mm.y, acc[3][b2 + 1]);       \
        }                                                          \
    } while (0)

// Qout >= 4: j0..j0+3 share c, q consecutive (float4 in-place)
__device__ __forceinline__ void sweep_step4(float* buf,
                                            const float* __restrict__ M,
                                            int Qout, int lq, int t)
{
    const int Qin = Qout << 1;
    const int j0 = t * 4;
    const int q0 = j0 & (Qout - 1);
    const int c  = j0 >> lq;

    uint64_t acc[4][10];
#pragma unroll
    for (int u = 0; u < 4; u++)
#pragma unroll
        for (int b2 = 0; b2 < 10; b2++) acc[u][b2] = 0ull;

    const int base = c * 10 * Qin + q0;
#pragma unroll
    for (int rr = 0; rr < 10; rr++) {
#pragma unroll
        for (int pb = 0; pb < 2; pb++) {
            float4 vv = *(const float4*)(buf + SWZ(base + rr * Qin + pb * Qout));
            const uint64_t* M2 = (const uint64_t*)(M + (rr * 2 + pb) * 20);
            SWEEP_FMA_CORE(M2, vv.x, vv.y, vv.z, vv.w);
        }
    }

#pragma unroll
    for (int b2 = 0; b2 < 10; b2++) {
        float2 f0 = u2f2(acc[0][b2]), f1 = u2f2(acc[1][b2]);
        float2 f2 = u2f2(acc[2][b2]), f3 = u2f2(acc[3][b2]);
        const int bbA = 2 * b2, bbB = 2 * b2 + 1;
        const int dA = bbA / 10, sA = bbA % 10;
        const int dB = bbB / 10, sB = bbB % 10;
        *(float4*)(buf + SWZ(((c * 2 + dA) * 10 + sA) * Qout + q0)) = make_float4(f0.x, f1.x, f2.x, f3.x);
        *(float4*)(buf + SWZ(((c * 2 + dB) * 10 + sB) * Qout + q0)) = make_float4(f0.y, f1.y, f2.y, f3.y);
    }
}

// Qout == 2: two c's (2t, 2t+1), q in {0,1}; u = cc*2 + q
__device__ __forceinline__ void sweep_step2(float* buf,
                                            const float* __restrict__ M,
                                            int t)
{
    const int c0 = 2 * t;
    uint64_t acc[4][10];
#pragma unroll
    for (int u = 0; u < 4; u++)
#pragma unroll
        for (int b2 = 0; b2 < 10; b2++) acc[u][b2] = 0ull;

#pragma unroll
    for (int rr = 0; rr < 10; rr++) {
#pragma unroll
        for (int pb = 0; pb < 2; pb++) {
            float2 vA = *(const float2*)(buf + SWZ(((c0 + 0) * 10 + rr) * 4 + pb * 2));
            float2 vB = *(const float2*)(buf + SWZ(((c0 + 1) * 10 + rr) * 4 + pb * 2));
            const uint64_t* M2 = (const uint64_t*)(M + (rr * 2 + pb) * 20);
            SWEEP_FMA_CORE(M2, vA.x, vA.y, vB.x, vB.y);
        }
    }

#pragma unroll
    for (int b2 = 0; b2 < 10; b2++) {
        float2 f0 = u2f2(acc[0][b2]), f1 = u2f2(acc[1][b2]);
        float2 f2 = u2f2(acc[2][b2]), f3 = u2f2(acc[3][b2]);
        const int bbA = 2 * b2, bbB = 2 * b2 + 1;
        const int dA = bbA / 10, sA = bbA % 10;
        const int dB = bbB / 10, sB = bbB % 10;
        *(float2*)(buf + SWZ((((c0 + 0) * 2 + dA) * 10 + sA) * 2)) = make_float2(f0.x, f1.x);
        *(float2*)(buf + SWZ((((c0 + 0) * 2 + dB) * 10 + sB) * 2)) = make_float2(f0.y, f1.y);
        *(float2*)(buf + SWZ((((c0 + 1) * 2 + dA) * 10 + sA) * 2)) = make_float2(f2.x, f3.x);
        *(float2*)(buf + SWZ((((c0 + 1) * 2 + dB) * 10 + sB) * 2)) = make_float2(f2.y, f3.y);
    }
}

// Qout == 1: four c's (4t..4t+3); per c the two p-bits are adjacent (float2)
__device__ __forceinline__ void sweep_step1(float* buf,
                                            const float* __restrict__ M,
                                            int t)
{
    const int c0 = 4 * t;
    uint64_t acc[4][10];
#pragma unroll
    for (int u = 0; u < 4; u++)
#pragma unroll
        for (int b2 = 0; b2 < 10; b2++) acc[u][b2] = 0ull;

#pragma unroll
    for (int rr = 0; rr < 10; rr++) {
        float2 v0 = *(const float2*)(buf + SWZ(((c0 + 0) * 10 + rr) * 2));
        float2 v1 = *(const float2*)(buf + SWZ(((c0 + 1) * 10 + rr) * 2));
        float2 v2 = *(const float2*)(buf + SWZ(((c0 + 2) * 10 + rr) * 2));
        float2 v3 = *(const float2*)(buf + SWZ(((c0 + 3) * 10 + rr) * 2));
        const uint64_t* M20 = (const uint64_t*)(M + (rr * 2 + 0) * 20);
        const uint64_t* M21 = (const uint64_t*)(M + (rr * 2 + 1) * 20);
        SWEEP_FMA_CORE(M20, v0.x, v1.x, v2.x, v3.x);
        SWEEP_FMA_CORE(M21, v0.y, v1.y, v2.y, v3.y);
    }

#pragma unroll
    for (int b2 = 0; b2 < 10; b2++) {
        const int bbA = 2 * b2, bbB = 2 * b2 + 1;
        const int dA = bbA / 10, sA = bbA % 10;
        const int dB = bbB / 10, sB = bbB % 10;
#pragma unroll
        for (int u = 0; u < 4; u++) {
            float2 f = u2f2(acc[u][b2]);
            buf[SWZ(((c0 + u) * 2 + dA) * 10 + sA)] = f.x;
            buf[SWZ(((c0 + u) * 2 + dB) * 10 + sB)] = f.y;
        }
    }
}

// ========================= Kernel 1: input sweep (in-place+SWZ, 128 thr, 57KB) =========================
__global__ __launch_bounds__(128, 4) void input_sweep_kernel(const float* __restrict__ x,
                                                             const float* __restrict__ ic)
{
    extern __shared__ float sm[];
    float* Mc  = sm;            // 4000 (16B aligned)
    float* buf = sm + 4000;     // 10240
    const int tid = threadIdx.x;    // 0..127
    const int bl = blockIdx.x;
    const int b = bl / 10, l = bl % 10;

    for (int t = tid; t < 4000; t += 128) Mc[t] = ic[t];
    __syncthreads();

    const float* xrow = x + b * 1024;
    for (int idx = tid; idx < 10240; idx += 128) {
        int q  = idx & 511;
        int cs = idx >> 9;
        int c = cs / 10, s = cs % 10;
        float w0 = Mc[((l * 2 + 0) * 2 + c) * 10 + s];
        float w1 = Mc[((l * 2 + 1) * 2 + c) * 10 + s];
        buf[SWZ(idx)] = xrow[q] * w0 + xrow[512 + q] * w1;
    }

    for (int i = 1; i <= 7; i++) {
        __syncthreads();
        sweep_step4(buf, Mc + i * 400, 512 >> i, 9 - i, tid);
    }
    __syncthreads();
    sweep_step2(buf, Mc + 8 * 400, tid);
    __syncthreads();
    sweep_step1(buf, Mc + 9 * 400, tid);
    __syncthreads();

    const size_t rowbase = (size_t)bl * 10;
    for (int idx = tid; idx < 5120; idx += 128) {
        int rr = idx / 512, cp2 = idx % 512;
        int c0 = cp2 * 2;
        float va = buf[SWZ(c0 * 10 + rr)];
        float vb = buf[SWZ((c0 + 1) * 10 + rr)];
        __nv_bfloat16 ha = __float2bfloat16(va);
        __nv_bfloat16 hb = __float2bfloat16(vb);
        __nv_bfloat16 la = __float2bfloat16(va - __bfloat162float(ha));
        __nv_bfloat16 lb = __float2bfloat16(vb - __bfloat162float(hb));
        size_t row = rowbase + rr;
        __nv_bfloat162 hi; hi.x = ha; hi.y = hb;
        __nv_bfloat162 lo; lo.x = la; lo.y = lb;
        *(__nv_bfloat162*)&g_A[row * 2048 + c0]        = hi;
        *(__nv_bfloat162*)&g_A[row * 2048 + 1024 + c0] = lo;
    }
}

// ========================= Kernel 2: B transpose+split =========================
__global__ __launch_bounds__(256) void bconv_kernel(const float* __restrict__ cc)
{
    __shared__ float t[32][33];
    const int tx = threadIdx.x, ty = threadIdx.y;   // (32, 8)
    const int c0 = blockIdx.x * 32, d0 = blockIdx.y * 32;
#pragma unroll
    for (int i = 0; i < 32; i += 8)
        t[ty + i][tx] = cc[(size_t)(c0 + ty + i) * 1024 + d0 + tx];
    __syncthreads();
#pragma unroll
    for (int i = 0; i < 32; i += 8) {
        int d = ty + i;
        float v = t[tx][d];   // central[c0+tx][d0+d]
        __nv_bfloat16 h = __float2bfloat16(v);
        __nv_bfloat16 lo = __float2bfloat16(v - __bfloat162float(h));
        g_Bt[(size_t)(d0 + d) * 2048 + c0 + tx]        = h;
        g_Bt[(size_t)(d0 + d) * 2048 + 1024 + c0 + tx] = lo;
    }
}

// ========================= Kernel 3: HMMA GEMM v3 — fused 3-term =========================
// U(51200x1024) = Ah·Bh + Al·Bh + Ah·Bl, one pass over K=1024.
// Per 32-col K-chunk, a stage holds Ah|Al and Bh|Bl packed in 128B rows:
//   A row r: [Ah(64B) | Al(64B)], B row r: [Bh(64B) | Bl(64B)]  -> 16KB + 16KB = 32KB/stage.
// CTA tile 128x128; 4 warps (2x2), warp tile 64x64; 3 stages = 96KB -> 2 CTAs/SM.
#define G_STAGES 3
#define G_ABYTES 16384            // 128 rows x 128B
#define G_BBYTES 16384
#define G_STAGE_BYTES (G_ABYTES + G_BBYTES)
#define G_NCHUNKS 32              // 1024 / 32

__device__ __forceinline__ void gemm_load_chunk(int kc, int stage, int m0, int n0,
                                                uint32_t smem_base, int tid)
{
    const uint32_t abase = smem_base + stage * G_STAGE_BYTES;
    const uint32_t bbase = abase + G_ABYTES;
    const int j32 = kc * 32;
#pragma unroll
    for (int i = 0; i < 8; i++) {                 // A: 1024 x 16B
        int idx = tid + i * 128;
        int r = idx >> 3, c = idx & 7;            // c 0-3: Ah, 4-7: Al
        int col = ((c & 4) ? 1024 : 0) + j32 + (c & 3) * 8;
        uint32_t dst = abase + (uint32_t)(r * 128 + ((c ^ (r & 7)) << 4));
        const void* src = (const void*)(g_A + (size_t)(m0 + r) * 2048 + col);
        CP_ASYNC16(dst, src);
    }
#pragma unroll
    for (int i = 0; i < 8; i++) {                 // B: 1024 x 16B
        int idx = tid + i * 128;
        int r = idx >> 3, c = idx & 7;            // c 0-3: Bh, 4-7: Bl
        int col = ((c & 4) ? 1024 : 0) + j32 + (c & 3) * 8;
        uint32_t dst = bbase + (uint32_t)(r * 128 + ((c ^ (r & 7)) << 4));
        const void* src = (const void*)(g_Bt + (size_t)(n0 + r) * 2048 + col);
        CP_ASYNC16(dst, src);
    }
}

__global__ __launch_bounds__(128, 2) void gemm_mma_kernel()
{
    extern __shared__ char smc[];
    const uint32_t smem_base = smem_to_u32(smc);
    const int tid  = threadIdx.x;
    const int wid  = tid >> 5;      // 0..3
    const int lane = tid & 31;
    const int m0 = blockIdx.y * 128;
    const int n0 = blockIdx.x * 128;
    const int wm = (wid & 1) * 64;      // warp row in tile
    const int wn = (wid >> 1) * 64;     // warp col in tile

    float acc[4][8][4];
#pragma unroll
    for (int i = 0; i < 4; i++)
#pragma unroll
        for (int j = 0; j < 8; j++)
#pragma unroll
            for (int k = 0; k < 4; k++) acc[i][j][k] = 0.f;

    // prologue: chunks 0,1 into stages 0,1
#pragma unroll
    for (int c = 0; c < 2; c++) { gemm_load_chunk(c, c, m0, n0, smem_base, tid); CP_COMMIT(); }

    const int matA = lane >> 3;
    const int rowA_lo = (lane & 7) + ((matA & 1) << 3);
    const int kselA = matA >> 1;
    const int matB = lane >> 3;
    const int rowB_lo = (lane & 7) + ((matB >> 1) << 3);
    const int kselB = matB & 1;

    int stage = 0, lstage = 2;
    for (int kc = 0; kc < G_NCHUNKS; kc++) {
        CP_WAIT(1);
        __syncthreads();
        int pre = kc + 2; if (pre > G_NCHUNKS - 1) pre = G_NCHUNKS - 1;
        gemm_load_chunk(pre, lstage, m0, n0, smem_base, tid);
        CP_COMMIT();

        const uint32_t abase = smem_base + stage * G_STAGE_BYTES;
        const uint32_t bbase = abase + G_ABYTES;

#pragma unroll
        for (int kk = 0; kk < 2; kk++) {
            uint32_t afh[4][4], afl[4][4];
#pragma unroll
            for (int mt = 0; mt < 4; mt++) {
                int r = wm + mt * 16 + rowA_lo;
                int chh = 2 * kk + kselA;           // Ah: chunks 0-3
                int chl = 4 + 2 * kk + kselA;       // Al: chunks 4-7
                uint32_t ah = abase + (uint32_t)(r * 128 + ((chh ^ (r & 7)) << 4));
                uint32_t al = abase + (uint32_t)(r * 128 + ((chl ^ (r & 7)) << 4));
                LDMATRIX_X4(afh[mt][0], afh[mt][1], afh[mt][2], afh[mt][3], ah);
                LDMATRIX_X4(afl[mt][0], afl[mt][1], afl[mt][2], afl[mt][3], al);
            }
            uint32_t bfh[4][4], bfl[4][4];
#pragma unroll
            for (int p = 0; p < 4; p++) {
                int r = wn + p * 16 + rowB_lo;
                int chh = 2 * kk + kselB;
                int chl = 4 + 2 * kk + kselB;
                uint32_t bh = bbase + (uint32_t)(r * 128 + ((chh ^ (r & 7)) << 4));
                uint32_t bl = bbase + (uint32_t)(r * 128 + ((chl ^ (r & 7)) << 4));
                LDMATRIX_X4(bfh[p][0], bfh[p][1], bfh[p][2], bfh[p][3], bh);
                LDMATRIX_X4(bfl[p][0], bfl[p][1], bfl[p][2], bfl[p][3], bl);
            }
            // pass 1: Ah * Bh
#pragma unroll
            for (int mt = 0; mt < 4; mt++)
#pragma unroll
                for (int nt = 0; nt < 8; nt++) {
                    int p = nt >> 1, hi = nt & 1;
                    MMA_BF16(acc[mt][nt][0], acc[mt][nt][1], acc[mt][nt][2], acc[mt][nt][3],
                             afh[mt][0], afh[mt][1], afh[mt][2], afh[mt][3],
                             bfh[p][2 * hi], bfh[p][2 * hi + 1]);
                }
            // pass 2: Al * Bh
#pragma unroll
            for (int mt = 0; mt < 4; mt++)
#pragma unroll
                for (int nt = 0; nt < 8; nt++) {
                    int p = nt >> 1, hi = nt & 1;
                    MMA_BF16(acc[mt][nt][0], acc[mt][nt][1], acc[mt][nt][2], acc[mt][nt][3],
                             afl[mt][0], afl[mt][1], afl[mt][2], afl[mt][3],
                             bfh[p][2 * hi], bfh[p][2 * hi + 1]);
                }
            // pass 3: Ah * Bl
#pragma unroll
            for (int mt = 0; mt < 4; mt++)
#pragma unroll
                for (int nt = 0; nt < 8; nt++) {
                    int p = nt >> 1, hi = nt & 1;
                    MMA_BF16(acc[mt][nt][0], acc[mt][nt][1], acc[mt][nt][2], acc[mt][nt][3],
                             afh[mt][0], afh[mt][1], afh[mt][2], afh[mt][3],
                             bfl[p][2 * hi], bfl[p][2 * hi + 1]);
                }
        }
        stage = (stage + 1 == 3) ? 0 : stage + 1;
        lstage = (lstage + 1 == 3) ? 0 : lstage + 1;
    }

    // epilogue
#pragma unroll
    for (int mt = 0; mt < 4; mt++) {
        int row = m0 + wm + mt * 16 + (lane >> 2);
#pragma unroll
        for (int nt = 0; nt < 8; nt++) {
            int col = n0 + wn + nt * 8 + (lane & 3) * 2;
            *(float2*)&g_U[(size_t)row * 1024 + col]       = make_float2(acc[mt][nt][0], acc[mt][nt][1]);
            *(float2*)&g_U[(size_t)(row + 8) * 1024 + col] = make_float2(acc[mt][nt][2], acc[mt][nt][3]);
        }
    }
}

// ========================= Kernel 4: output sweep (in-place+SWZ, 128 thr, 57KB) =========================
__global__ __launch_bounds__(128, 4) void output_sweep_kernel(const float* __restrict__ oc)
{
    extern __shared__ float sm[];
    float* Mc  = sm;            // 4000 (permuted)
    float* buf = sm + 4000;     // 10240
    const int tid = threadIdx.x;    // 0..127
    const int bl = blockIdx.x;
    const int l = bl % 10;
    const size_t rowbase = (size_t)bl * 10;

    for (int t = tid; t < 4000; t += 128) {
        int j = t / 400, rem = t % 400;
        int a = rem / 20, bc = rem % 20;
        int rr = a >> 1, d = a & 1, p = bc / 10, s = bc % 10;
        Mc[t] = oc[j * 400 + rr * 40 + p * 20 + d * 10 + s];
    }
    for (int idx = tid; idx < 10240; idx += 128)
        buf[SWZ(idx)] = g_U[rowbase * 1024 + idx];
    __syncthreads();

    for (int j = 0; j <= 7; j++) {
        sweep_step4(buf, Mc + j * 400, 512 >> j, 9 - j, tid);
        __syncthreads();
    }
    sweep_step2(buf, Mc + 8 * 400, tid);
    __syncthreads();
    sweep_step1(buf, Mc + 9 * 400, tid);
    __syncthreads();

    for (int p = tid; p < 1024; p += 128)
        g_P[(size_t)bl * 1024 + p] = buf[SWZ(p * 10 + l)];
}

// ========================= Kernel 5: reduce =========================
__global__ __launch_bounds__(256) void reduce_kernel(const float* __restrict__ bias,
                                                     float* __restrict__ out)
{
    const int b = blockIdx.x;
    for (int p = threadIdx.x; p < 1024; p += 256) {
        float s = bias[p];
#pragma unroll
        for (int l = 0; l < 10; l++) s += g_P[(size_t)(b * 10 + l) * 1024 + p];
        out[b * 1024 + p] = s;
    }
}

// ========================= launch =========================
extern "C" void kernel_launch(void* const* d_in, const int* in_sizes, int n_in,
                              void* d_out, int out_size)
{
    (void)in_sizes; (void)n_in; (void)out_size;
    const float* x    = (const float*)d_in[0];
    const float* ic   = (const float*)d_in[1];
    const float* oc   = (const float*)d_in[2];
    const float* cc   = (const float*)d_in[3];
    const float* bias = (const float*)d_in[4];
    float* out = (float*)d_out;

    const int SMEM_SWEEP = (4000 + 10240) * 4;              // 56960 B -> 4 CTAs/SM
    const int SMEM_GEMM  = G_STAGES * G_STAGE_BYTES;        // 98304 B -> 2 CTAs/SM
    cudaFuncSetAttribute(input_sweep_kernel,  cudaFuncAttributeMaxDynamicSharedMemorySize, SMEM_SWEEP);
    cudaFuncSetAttribute(output_sweep_kernel, cudaFuncAttributeMaxDynamicSharedMemorySize, SMEM_SWEEP);
    cudaFuncSetAttribute(gemm_mma_kernel,     cudaFuncAttributeMaxDynamicSharedMemorySize, SMEM_GEMM);

    input_sweep_kernel<<<5120, 128, SMEM_SWEEP>>>(x, ic);
    bconv_kernel<<<dim3(32, 32), dim3(32, 8)>>>(cc);
    gemm_mma_kernel<<<dim3(8, 400), 128, SMEM_GEMM>>>();
    output_sweep_kernel<<<5120, 128, SMEM_SWEEP>>>(oc);
    reduce_kernel<<<512, 256>>>(bias, out);
}

// round 15
// speedup vs baseline: 1.1041x; 1.1041x over previous
#include <cuda_runtime.h>
#include <cuda_fp16.h>
#include <cstdint>

// Problem constants
//   x: (512,1024) f32; input/output_cores: (10,10,2,2,10) f32
//   central: (1024,1024) f32; bias: (1,1024) f32; out: (512,1024) f32
#define MROWS 51200   // 512 * 10 (l0) * 10 (r)

// Scratch (device globals: allocation-free kernel_launch)
__device__ __half g_A [(size_t)MROWS * 2048];   // [Ah | Al] fp16 per row
__device__ __half g_Bt[(size_t)1024 * 1024];    // Bh fp16, Bt[d][c] = central[c][d]
__device__ float  g_U [(size_t)MROWS * 1024];   // U = S @ central
__device__ float  g_P [(size_t)5120 * 1024];    // per-(b,l) partials

// ========================= helpers =========================
__device__ __forceinline__ uint32_t smem_to_u32(const void* p) {
    uint32_t a;
    asm("{ .reg .u64 t; cvta.to.shared.u64 t, %1; cvt.u32.u64 %0, t; }" : "=r"(a) : "l"(p));
    return a;
}
#define CP_ASYNC16(dst, src) \
    asm volatile("cp.async.cg.shared.global [%0], [%1], 16;" :: "r"(dst), "l"(src) : "memory")
#define CP_COMMIT() asm volatile("cp.async.commit_group;" ::: "memory")
#define CP_WAIT(n)  asm volatile("cp.async.wait_group %0;" :: "n"(n) : "memory")
#define LDMATRIX_X4(r0, r1, r2, r3, addr) \
    asm volatile("ldmatrix.sync.aligned.m8n8.x4.shared.b16 {%0,%1,%2,%3}, [%4];" \
                 : "=r"(r0), "=r"(r1), "=r"(r2), "=r"(r3) : "r"(addr))
#define MMA_FP16(c0, c1, c2, c3, a0, a1, a2, a3, b0, b1) \
    asm volatile("mma.sync.aligned.m16n8k16.row.col.f32.f16.f16.f32 " \
                 "{%0,%1,%2,%3}, {%4,%5,%6,%7}, {%8,%9}, {%0,%1,%2,%3};" \
                 : "+f"(c0), "+f"(c1), "+f"(c2), "+f"(c3) \
                 : "r"(a0), "r"(a1), "r"(a2), "r"(a3), "r"(b0), "r"(b1))

// f32x2 helpers
__device__ __forceinline__ uint64_t f2dup(float x) {
    uint64_t r; asm("mov.b64 %0, {%1, %1};" : "=l"(r) : "f"(x)); return r;
}
__device__ __forceinline__ uint64_t fma2(uint64_t a, uint64_t b, uint64_t c) {
    uint64_t d; asm("fma.rn.f32x2 %0, %1, %2, %3;" : "=l"(d) : "l"(a), "l"(b), "l"(c)); return d;
}
__device__ __forceinline__ float2 u2f2(uint64_t u) {
    float2 f; asm("mov.b64 {%0, %1}, %2;" : "=f"(f.x), "=f"(f.y) : "l"(u)); return f;
}

// State-buffer bank swizzle: XOR quad-index bits [3:6) into [0:3).
__device__ __forceinline__ int SWZ(int w) { return w ^ ((w >> 3) & 28); }

// ========================= sweep steps (IN-PLACE + SWZ, 128 threads, 4 outputs/thread) ==========
// State: flat[(C_idx*10 + bond)*Q + q] (pre-swizzle). M: 20x20, M[(r*2+p)*20 + (d*10+s)].

#define SWEEP_FMA_CORE(M2, v0f, v1f, v2f, v3f)                     \
    do {                                                           \
        uint64_t d0 = f2dup(v0f), d1 = f2dup(v1f);                 \
        uint64_t d2 = f2dup(v2f), d3 = f2dup(v3f);                 \
        _Pragma("unroll")                                          \
        for (int b2 = 0; b2 < 10; b2 += 2) {                       \
            ulonglong2 mm = *(const ulonglong2*)((M2) + b2);       \
            acc[0][b2]     = fma2(d0, mm.x, acc[0][b2]);           \
            acc[1][b2]     = fma2(d1, mm.x, acc[1][b2]);           \
            acc[2][b2]     = fma2(d2, mm.x, acc[2][b2]);           \
            acc[3][b2]     = fma2(d3, mm.x, acc[3][b2]);           \
            acc[0][b2 + 1] = fma2(d0, mm.y, acc[0][b2 + 1]);       \
            acc[1][b2 + 1] = fma2(d1, mm.y, acc[1][b2 + 1]);       \
            acc[2][b2 + 1] = fma2(d2, mm.y, acc[2][b2 + 1]);       \
            acc[3][b2 + 1] = fma2(d3, mm.y, acc[3][b2 + 1]);       \
        }                                                          \
    } while (0)

// Qout >= 4: j0..j0+3 share c, q consecutive (float4 in-place)
__device__ __forceinline__ void sweep_step4(float* buf,
                                            const float* __restrict__ M,
                                            int Qout, int lq, int t)
{
    const int Qin = Qout << 1;
    const int j0 = t * 4;
    const int q0 = j0 & (Qout - 1);
    const int c  = j0 >> lq;

    uint64_t acc[4][10];
#pragma unroll
    for (int u = 0; u < 4; u++)
#pragma unroll
        for (int b2 = 0; b2 < 10; b2++) acc[u][b2] = 0ull;

    const int base = c * 10 * Qin + q0;
#pragma unroll
    for (int rr = 0; rr < 10; rr++) {
#pragma unroll
        for (int pb = 0; pb < 2; pb++) {
            float4 vv = *(const float4*)(buf + SWZ(base + rr * Qin + pb * Qout));
            const uint64_t* M2 = (const uint64_t*)(M + (rr * 2 + pb) * 20);
            SWEEP_FMA_CORE(M2, vv.x, vv.y, vv.z, vv.w);
        }
    }

#pragma unroll
    for (int b2 = 0; b2 < 10; b2++) {
        float2 f0 = u2f2(acc[0][b2]), f1 = u2f2(acc[1][b2]);
        float2 f2 = u2f2(acc[2][b2]), f3 = u2f2(acc[3][b2]);
        const int bbA = 2 * b2, bbB = 2 * b2 + 1;
        const int dA = bbA / 10, sA = bbA % 10;
        const int dB = bbB / 10, sB = bbB % 10;
        *(float4*)(buf + SWZ(((c * 2 + dA) * 10 + sA) * Qout + q0)) = make_float4(f0.x, f1.x, f2.x, f3.x);
        *(float4*)(buf + SWZ(((c * 2 + dB) * 10 + sB) * Qout + q0)) = make_float4(f0.y, f1.y, f2.y, f3.y);
    }
}

// Qout == 2: two c's (2t, 2t+1), q in {0,1}; u = cc*2 + q
__device__ __forceinline__ void sweep_step2(float* buf,
                                            const float* __restrict__ M,
                                            int t)
{
    const int c0 = 2 * t;
    uint64_t acc[4][10];
#pragma unroll
    for (int u = 0; u < 4; u++)
#pragma unroll
        for (int b2 = 0; b2 < 10; b2++) acc[u][b2] = 0ull;

#pragma unroll
    for (int rr = 0; rr < 10; rr++) {
#pragma unroll
        for (int pb = 0; pb < 2; pb++) {
            float2 vA = *(const float2*)(buf + SWZ(((c0 + 0) * 10 + rr) * 4 + pb * 2));
            float2 vB = *(const float2*)(buf + SWZ(((c0 + 1) * 10 + rr) * 4 + pb * 2));
            const uint64_t* M2 = (const uint64_t*)(M + (rr * 2 + pb) * 20);
            SWEEP_FMA_CORE(M2, vA.x, vA.y, vB.x, vB.y);
        }
    }

#pragma unroll
    for (int b2 = 0; b2 < 10; b2++) {
        float2 f0 = u2f2(acc[0][b2]), f1 = u2f2(acc[1][b2]);
        float2 f2 = u2f2(acc[2][b2]), f3 = u2f2(acc[3][b2]);
        const int bbA = 2 * b2, bbB = 2 * b2 + 1;
        const int dA = bbA / 10, sA = bbA % 10;
        const int dB = bbB / 10, sB = bbB % 10;
        *(float2*)(buf + SWZ((((c0 + 0) * 2 + dA) * 10 + sA) * 2)) = make_float2(f0.x, f1.x);
        *(float2*)(buf + SWZ((((c0 + 0) * 2 + dB) * 10 + sB) * 2)) = make_float2(f0.y, f1.y);
        *(float2*)(buf + SWZ((((c0 + 1) * 2 + dA) * 10 + sA) * 2)) = make_float2(f2.x, f3.x);
        *(float2*)(buf + SWZ((((c0 + 1) * 2 + dB) * 10 + sB) * 2)) = make_float2(f2.y, f3.y);
    }
}

// Qout == 1: four c's (4t..4t+3); per c the two p-bits are adjacent (float2)
__device__ __forceinline__ void sweep_step1(float* buf,
                                            const float* __restrict__ M,
                                            int t)
{
    const int c0 = 4 * t;
    uint64_t acc[4][10];
#pragma unroll
    for (int u = 0; u < 4; u++)
#pragma unroll
        for (int b2 = 0; b2 < 10; b2++) acc[u][b2] = 0ull;

#pragma unroll
    for (int rr = 0; rr < 10; rr++) {
        float2 v0 = *(const float2*)(buf + SWZ(((c0 + 0) * 10 + rr) * 2));
        float2 v1 = *(const float2*)(buf + SWZ(((c0 + 1) * 10 + rr) * 2));
        float2 v2 = *(const float2*)(buf + SWZ(((c0 + 2) * 10 + rr) * 2));
        float2 v3 = *(const float2*)(buf + SWZ(((c0 + 3) * 10 + rr) * 2));
        const uint64_t* M20 = (const uint64_t*)(M + (rr * 2 + 0) * 20);
        const uint64_t* M21 = (const uint64_t*)(M + (rr * 2 + 1) * 20);
        SWEEP_FMA_CORE(M20, v0.x, v1.x, v2.x, v3.x);
        SWEEP_FMA_CORE(M21, v0.y, v1.y, v2.y, v3.y);
    }

#pragma unroll
    for (int b2 = 0; b2 < 10; b2++) {
        const int bbA = 2 * b2, bbB = 2 * b2 + 1;
        const int dA = bbA / 10, sA = bbA % 10;
        const int dB = bbB / 10, sB = bbB % 10;
#pragma unroll
        for (int u = 0; u < 4; u++) {
            float2 f = u2f2(acc[u][b2]);
            buf[SWZ(((c0 + u) * 2 + dA) * 10 + sA)] = f.x;
            buf[SWZ(((c0 + u) * 2 + dB) * 10 + sB)] = f.y;
        }
    }
}

// ========================= Kernel 1: input sweep (in-place+SWZ, 128 thr, 57KB) =========================
__global__ __launch_bounds__(128, 4) void input_sweep_kernel(const float* __restrict__ x,
                                                             const float* __restrict__ ic)
{
    extern __shared__ float sm[];
    float* Mc  = sm;            // 4000 (16B aligned)
    float* buf = sm + 4000;     // 10240
    const int tid = threadIdx.x;    // 0..127
    const int bl = blockIdx.x;
    const int b = bl / 10, l = bl % 10;

    for (int t = tid; t < 4000; t += 128) Mc[t] = ic[t];
    __syncthreads();

    const float* xrow = x + b * 1024;
    for (int idx = tid; idx < 10240; idx += 128) {
        int q  = idx & 511;
        int cs = idx >> 9;
        int c = cs / 10, s = cs % 10;
        float w0 = Mc[((l * 2 + 0) * 2 + c) * 10 + s];
        float w1 = Mc[((l * 2 + 1) * 2 + c) * 10 + s];
        buf[SWZ(idx)] = xrow[q] * w0 + xrow[512 + q] * w1;
    }

    for (int i = 1; i <= 7; i++) {
        __syncthreads();
        sweep_step4(buf, Mc + i * 400, 512 >> i, 9 - i, tid);
    }
    __syncthreads();
    sweep_step2(buf, Mc + 8 * 400, tid);
    __syncthreads();
    sweep_step1(buf, Mc + 9 * 400, tid);
    __syncthreads();

    // final: buf[c*10 + r] -> fp16 hi/lo rows of g_A
    const size_t rowbase = (size_t)bl * 10;
    for (int idx = tid; idx < 5120; idx += 128) {
        int rr = idx / 512, cp2 = idx % 512;
        int c0 = cp2 * 2;
        float va = buf[SWZ(c0 * 10 + rr)];
        float vb = buf[SWZ((c0 + 1) * 10 + rr)];
        __half ha = __float2half(va);
        __half hb = __float2half(vb);
        __half la = __float2half(va - __half2float(ha));
        __half lb = __float2half(vb - __half2float(hb));
        size_t row = rowbase + rr;
        __half2 hi; hi.x = ha; hi.y = hb;
        __half2 lo; lo.x = la; lo.y = lb;
        *(__half2*)&g_A[row * 2048 + c0]        = hi;
        *(__half2*)&g_A[row * 2048 + 1024 + c0] = lo;
    }
}

// ========================= Kernel 2: B transpose (fp16) =========================
__global__ __launch_bounds__(256) void bconv_kernel(const float* __restrict__ cc)
{
    __shared__ float t[32][33];
    const int tx = threadIdx.x, ty = threadIdx.y;   // (32, 8)
    const int c0 = blockIdx.x * 32, d0 = blockIdx.y * 32;
#pragma unroll
    for (int i = 0; i < 32; i += 8)
        t[ty + i][tx] = cc[(size_t)(c0 + ty + i) * 1024 + d0 + tx];
    __syncthreads();
#pragma unroll
    for (int i = 0; i < 32; i += 8) {
        int d = ty + i;
        float v = t[tx][d];   // central[c0+tx][d0+d]
        g_Bt[(size_t)(d0 + d) * 1024 + c0 + tx] = __float2half(v);
    }
}

// ========================= Kernel 3: HMMA GEMM v4 — fp16 2-term =========================
// U(51200x1024) = (Ah + Al) @ Bh^T, virtual K = 2048 (block 0: Ah, block 1: Al; B = Bh both).
// CTA tile 128x128; 4 warps (2x2), warp tile 64x64; K-chunks of 64; 3 stages x 32KB -> 2 CTAs/SM.
#define G_STAGES 3
#define G_ABYTES 16384            // 128 rows x 128B (64 fp16)
#define G_BBYTES 16384
#define G_STAGE_BYTES (G_ABYTES + G_BBYTES)
#define G_NCHUNKS 32              // 2048 / 64

__device__ __forceinline__ void gemm_load_chunk(int kc, int stage, int m0, int n0,
                                                uint32_t smem_base, int tid)
{
    const int block = kc >> 4, j = kc & 15;
    const int acol = (block ? 1024 : 0) + j * 64;
    const int bcol = j * 64;
    const uint32_t abase = smem_base + stage * G_STAGE_BYTES;
    const uint32_t bbase = abase + G_ABYTES;
#pragma unroll
    for (int i = 0; i < 8; i++) {                 // A: 1024 x 16B
        int idx = tid + i * 128;
        int r = idx >> 3, c = idx & 7;
        uint32_t dst = abase + (uint32_t)(r * 128 + ((c ^ (r & 7)) << 4));
        const void* src = (const void*)(g_A + (size_t)(m0 + r) * 2048 + acol + c * 8);
        CP_ASYNC16(dst, src);
    }
#pragma unroll
    for (int i = 0; i < 8; i++) {                 // B: 1024 x 16B
        int idx = tid + i * 128;
        int r = idx >> 3, c = idx & 7;
        uint32_t dst = bbase + (uint32_t)(r * 128 + ((c ^ (r & 7)) << 4));
        const void* src = (const void*)(g_Bt + (size_t)(n0 + r) * 1024 + bcol + c * 8);
        CP_ASYNC16(dst, src);
    }
}

__global__ __launch_bounds__(128, 2) void gemm_mma_kernel()
{
    extern __shared__ char smc[];
    const uint32_t smem_base = smem_to_u32(smc);
    const int tid  = threadIdx.x;
    const int wid  = tid >> 5;      // 0..3
    const int lane = tid & 31;
    const int m0 = blockIdx.y * 128;
    const int n0 = blockIdx.x * 128;
    const int wm = (wid & 1) * 64;      // warp row in tile
    const int wn = (wid >> 1) * 64;     // warp col in tile

    float acc[4][8][4];
#pragma unroll
    for (int i = 0; i < 4; i++)
#pragma unroll
        for (int j = 0; j < 8; j++)
#pragma unroll
            for (int k = 0; k < 4; k++) acc[i][j][k] = 0.f;

    // prologue: chunks 0,1 into stages 0,1
#pragma unroll
    for (int c = 0; c < 2; c++) { gemm_load_chunk(c, c, m0, n0, smem_base, tid); CP_COMMIT(); }

    const int matA = lane >> 3;
    const int rowA_lo = (lane & 7) + ((matA & 1) << 3);
    const int kselA = matA >> 1;
    const int matB = lane >> 3;
    const int rowB_lo = (lane & 7) + ((matB >> 1) << 3);
    const int kselB = matB & 1;

    int stage = 0, lstage = 2;
    for (int kc = 0; kc < G_NCHUNKS; kc++) {
        CP_WAIT(1);
        __syncthreads();
        int pre = kc + 2; if (pre > G_NCHUNKS - 1) pre = G_NCHUNKS - 1;
        gemm_load_chunk(pre, lstage, m0, n0, smem_base, tid);
        CP_COMMIT();

        const uint32_t abase = smem_base + stage * G_STAGE_BYTES;
        const uint32_t bbase = abase + G_ABYTES;

#pragma unroll
        for (int kk = 0; kk < 4; kk++) {
            uint32_t af[4][4];
#pragma unroll
            for (int mt = 0; mt < 4; mt++) {
                int r = wm + mt * 16 + rowA_lo;
                int ch = 2 * kk + kselA;
                uint32_t addr = abase + (uint32_t)(r * 128 + ((ch ^ (r & 7)) << 4));
                LDMATRIX_X4(af[mt][0], af[mt][1], af[mt][2], af[mt][3], addr);
            }
            uint32_t bf[4][4];
#pragma unroll
            for (int p = 0; p < 4; p++) {
                int r = wn + p * 16 + rowB_lo;
                int ch = 2 * kk + kselB;
                uint32_t addr = bbase + (uint32_t)(r * 128 + ((ch ^ (r & 7)) << 4));
                LDMATRIX_X4(bf[p][0], bf[p][1], bf[p][2], bf[p][3], addr);
            }
#pragma unroll
            for (int mt = 0; mt < 4; mt++)
#pragma unroll
                for (int nt = 0; nt < 8; nt++) {
                    int p = nt >> 1, hi = nt & 1;
                    MMA_FP16(acc[mt][nt][0], acc[mt][nt][1], acc[mt][nt][2], acc[mt][nt][3],
                             af[mt][0], af[mt][1], af[mt][2], af[mt][3],
                             bf[p][2 * hi], bf[p][2 * hi + 1]);
                }
        }
        stage = (stage + 1 == 3) ? 0 : stage + 1;
        lstage = (lstage + 1 == 3) ? 0 : lstage + 1;
    }

    // epilogue
#pragma unroll
    for (int mt = 0; mt < 4; mt++) {
        int row = m0 + wm + mt * 16 + (lane >> 2);
#pragma unroll
        for (int nt = 0; nt < 8; nt++) {
            int col = n0 + wn + nt * 8 + (lane & 3) * 2;
            *(float2*)&g_U[(size_t)row * 1024 + col]       = make_float2(acc[mt][nt][0], acc[mt][nt][1]);
            *(float2*)&g_U[(size_t)(row + 8) * 1024 + col] = make_float2(acc[mt][nt][2], acc[mt][nt][3]);
        }
    }
}

// ========================= Kernel 4: output sweep (in-place+SWZ, 128 thr, 57KB) =========================
__global__ __launch_bounds__(128, 4) void output_sweep_kernel(const float* __restrict__ oc)
{
    extern __shared__ float sm[];
    float* Mc  = sm;            // 4000 (permuted)
    float* buf = sm + 4000;     // 10240
    const int tid = threadIdx.x;    // 0..127
    const int bl = blockIdx.x;
    const int l = bl % 10;
    const size_t rowbase = (size_t)bl * 10;

    for (int t = tid; t < 4000; t += 128) {
        int j = t / 400, rem = t % 400;
        int a = rem / 20, bc = rem % 20;
        int rr = a >> 1, d = a & 1, p = bc / 10, s = bc % 10;
        Mc[t] = oc[j * 400 + rr * 40 + p * 20 + d * 10 + s];
    }
    for (int idx = tid; idx < 10240; idx += 128)
        buf[SWZ(idx)] = g_U[rowbase * 1024 + idx];
    __syncthreads();

    for (int j = 0; j <= 7; j++) {
        sweep_step4(buf, Mc + j * 400, 512 >> j, 9 - j, tid);
        __syncthreads();
    }
    sweep_step2(buf, Mc + 8 * 400, tid);
    __syncthreads();
    sweep_step1(buf, Mc + 9 * 400, tid);
    __syncthreads();

    for (int p = tid; p < 1024; p += 128)
        g_P[(size_t)bl * 1024 + p] = buf[SWZ(p * 10 + l)];
}

// ========================= Kernel 5: reduce =========================
__global__ __launch_bounds__(256) void reduce_kernel(const float* __restrict__ bias,
                                                     float* __restrict__ out)
{
    const int b = blockIdx.x;
    for (int p = threadIdx.x; p < 1024; p += 256) {
        float s = bias[p];
#pragma unroll
        for (int l = 0; l < 10; l++) s += g_P[(size_t)(b * 10 + l) * 1024 + p];
        out[b * 1024 + p] = s;
    }
}

// ========================= launch =========================
extern "C" void kernel_launch(void* const* d_in, const int* in_sizes, int n_in,
                              void* d_out, int out_size)
{
    (void)in_sizes; (void)n_in; (void)out_size;
    const float* x    = (const float*)d_in[0];
    const float* ic   = (const float*)d_in[1];
    const float* oc   = (const float*)d_in[2];
    const float* cc   = (const float*)d_in[3];
    const float* bias = (const float*)d_in[4];
    float* out = (float*)d_out;

    const int SMEM_SWEEP = (4000 + 10240) * 4;              // 56960 B -> 4 CTAs/SM
    const int SMEM_GEMM  = G_STAGES * G_STAGE_BYTES;        // 98304 B -> 2 CTAs/SM
    cudaFuncSetAttribute(input_sweep_kernel,  cudaFuncAttributeMaxDynamicSharedMemorySize, SMEM_SWEEP);
    cudaFuncSetAttribute(output_sweep_kernel, cudaFuncAttributeMaxDynamicSharedMemorySize, SMEM_SWEEP);
    cudaFuncSetAttribute(gemm_mma_kernel,     cudaFuncAttributeMaxDynamicSharedMemorySize, SMEM_GEMM);

    input_sweep_kernel<<<5120, 128, SMEM_SWEEP>>>(x, ic);
    bconv_kernel<<<dim3(32, 32), dim3(32, 8)>>>(cc);
    gemm_mma_kernel<<<dim3(8, 400), 128, SMEM_GEMM>>>();
    output_sweep_kernel<<<5120, 128, SMEM_SWEEP>>>(oc);
    reduce_kernel<<<512, 256>>>(bias, out);
}

// round 16
// speedup vs baseline: 1.4073x; 1.2747x over previous
#include <cuda_runtime.h>
#include <cuda_fp16.h>
#include <cstdint>

// Problem constants
//   x: (512,1024) f32; input/output_cores: (10,10,2,2,10) f32
//   central: (1024,1024) f32; bias: (1,1024) f32; out: (512,1024) f32
#define MROWS 51200   // 512 * 10 (l0) * 10 (r)

// Scratch (device globals: allocation-free kernel_launch)
__device__ __half g_A [(size_t)MROWS * 1024];   // A fp16 (rounded S)
__device__ __half g_Bt[(size_t)1024 * 1024];    // Bh fp16, Bt[d][c] = central[c][d]
__device__ float  g_U [(size_t)MROWS * 1024];   // U = S @ central
__device__ float  g_P [(size_t)5120 * 1024];    // per-(b,l) partials

// ========================= helpers =========================
__device__ __forceinline__ uint32_t smem_to_u32(const void* p) {
    uint32_t a;
    asm("{ .reg .u64 t; cvta.to.shared.u64 t, %1; cvt.u32.u64 %0, t; }" : "=r"(a) : "l"(p));
    return a;
}
#define CP_ASYNC16(dst, src) \
    asm volatile("cp.async.cg.shared.global [%0], [%1], 16;" :: "r"(dst), "l"(src) : "memory")
#define CP_COMMIT() asm volatile("cp.async.commit_group;" ::: "memory")
#define CP_WAIT(n)  asm volatile("cp.async.wait_group %0;" :: "n"(n) : "memory")
#define LDMATRIX_X4(r0, r1, r2, r3, addr) \
    asm volatile("ldmatrix.sync.aligned.m8n8.x4.shared.b16 {%0,%1,%2,%3}, [%4];" \
                 : "=r"(r0), "=r"(r1), "=r"(r2), "=r"(r3) : "r"(addr))
#define MMA_FP16(c0, c1, c2, c3, a0, a1, a2, a3, b0, b1) \
    asm volatile("mma.sync.aligned.m16n8k16.row.col.f32.f16.f16.f32 " \
                 "{%0,%1,%2,%3}, {%4,%5,%6,%7}, {%8,%9}, {%0,%1,%2,%3};" \
                 : "+f"(c0), "+f"(c1), "+f"(c2), "+f"(c3) \
                 : "r"(a0), "r"(a1), "r"(a2), "r"(a3), "r"(b0), "r"(b1))

// f32x2 helpers
__device__ __forceinline__ uint64_t f2dup(float x) {
    uint64_t r; asm("mov.b64 %0, {%1, %1};" : "=l"(r) : "f"(x)); return r;
}
__device__ __forceinline__ uint64_t fma2(uint64_t a, uint64_t b, uint64_t c) {
    uint64_t d; asm("fma.rn.f32x2 %0, %1, %2, %3;" : "=l"(d) : "l"(a), "l"(b), "l"(c)); return d;
}
__device__ __forceinline__ float2 u2f2(uint64_t u) {
    float2 f; asm("mov.b64 {%0, %1}, %2;" : "=f"(f.x), "=f"(f.y) : "l"(u)); return f;
}

// State-buffer bank swizzle: XOR quad-index bits [3:6) into [0:3).
__device__ __forceinline__ int SWZ(int w) { return w ^ ((w >> 3) & 28); }

// ========================= sweep steps (IN-PLACE + SWZ, 128 threads, 4 outputs/thread) ==========
// State: flat[(C_idx*10 + bond)*Q + q] (pre-swizzle). M: 20x20, M[(r*2+p)*20 + (d*10+s)].

#define SWEEP_FMA_CORE(M2, v0f, v1f, v2f, v3f)                     \
    do {                                                           \
        uint64_t d0 = f2dup(v0f), d1 = f2dup(v1f);                 \
        uint64_t d2 = f2dup(v2f), d3 = f2dup(v3f);                 \
        _Pragma("unroll")                                          \
        for (int b2 = 0; b2 < 10; b2 += 2) {                       \
            ulonglong2 mm = *(const ulonglong2*)((M2) + b2);       \
            acc[0][b2]     = fma2(d0, mm.x, acc[0][b2]);           \
            acc[1][b2]     = fma2(d1, mm.x, acc[1][b2]);           \
            acc[2][b2]     = fma2(d2, mm.x, acc[2][b2]);           \
            acc[3][b2]     = fma2(d3, mm.x, acc[3][b2]);           \
            acc[0][b2 + 1] = fma2(d0, mm.y, acc[0][b2 + 1]);       \
            acc[1][b2 + 1] = fma2(d1, mm.y, acc[1][b2 + 1]);       \
            acc[2][b2 + 1] = fma2(d2, mm.y, acc[2][b2 + 1]);       \
            acc[3][b2 + 1] = fma2(d3, mm.y, acc[3][b2 + 1]);       \
        }                                                          \
    } while (0)

// Qout >= 4: j0..j0+3 share c, q consecutive (float4 in-place)
__device__ __forceinline__ void sweep_step4(float* buf,
                                            const float* __restrict__ M,
                                            int Qout, int lq, int t)
{
    const int Qin = Qout << 1;
    const int j0 = t * 4;
    const int q0 = j0 & (Qout - 1);
    const int c  = j0 >> lq;

    uint64_t acc[4][10];
#pragma unroll
    for (int u = 0; u < 4; u++)
#pragma unroll
        for (int b2 = 0; b2 < 10; b2++) acc[u][b2] = 0ull;

    const int base = c * 10 * Qin + q0;
#pragma unroll
    for (int rr = 0; rr < 10; rr++) {
#pragma unroll
        for (int pb = 0; pb < 2; pb++) {
            float4 vv = *(const float4*)(buf + SWZ(base + rr * Qin + pb * Qout));
            const uint64_t* M2 = (const uint64_t*)(M + (rr * 2 + pb) * 20);
            SWEEP_FMA_CORE(M2, vv.x, vv.y, vv.z, vv.w);
        }
    }

#pragma unroll
    for (int b2 = 0; b2 < 10; b2++) {
        float2 f0 = u2f2(acc[0][b2]), f1 = u2f2(acc[1][b2]);
        float2 f2 = u2f2(acc[2][b2]), f3 = u2f2(acc[3][b2]);
        const int bbA = 2 * b2, bbB = 2 * b2 + 1;
        const int dA = bbA / 10, sA = bbA % 10;
        const int dB = bbB / 10, sB = bbB % 10;
        *(float4*)(buf + SWZ(((c * 2 + dA) * 10 + sA) * Qout + q0)) = make_float4(f0.x, f1.x, f2.x, f3.x);
        *(float4*)(buf + SWZ(((c * 2 + dB) * 10 + sB) * Qout + q0)) = make_float4(f0.y, f1.y, f2.y, f3.y);
    }
}

// Qout == 2: two c's (2t, 2t+1), q in {0,1}; u = cc*2 + q
__device__ __forceinline__ void sweep_step2(float* buf,
                                            const float* __restrict__ M,
                                            int t)
{
    const int c0 = 2 * t;
    uint64_t acc[4][10];
#pragma unroll
    for (int u = 0; u < 4; u++)
#pragma unroll
        for (int b2 = 0; b2 < 10; b2++) acc[u][b2] = 0ull;

#pragma unroll
    for (int rr = 0; rr < 10; rr++) {
#pragma unroll
        for (int pb = 0; pb < 2; pb++) {
            float2 vA = *(const float2*)(buf + SWZ(((c0 + 0) * 10 + rr) * 4 + pb * 2));
            float2 vB = *(const float2*)(buf + SWZ(((c0 + 1) * 10 + rr) * 4 + pb * 2));
            const uint64_t* M2 = (const uint64_t*)(M + (rr * 2 + pb) * 20);
            SWEEP_FMA_CORE(M2, vA.x, vA.y, vB.x, vB.y);
        }
    }

#pragma unroll
    for (int b2 = 0; b2 < 10; b2++) {
        float2 f0 = u2f2(acc[0][b2]), f1 = u2f2(acc[1][b2]);
        float2 f2 = u2f2(acc[2][b2]), f3 = u2f2(acc[3][b2]);
        const int bbA = 2 * b2, bbB = 2 * b2 + 1;
        const int dA = bbA / 10, sA = bbA % 10;
        const int dB = bbB / 10, sB = bbB % 10;
        *(float2*)(buf + SWZ((((c0 + 0) * 2 + dA) * 10 + sA) * 2)) = make_float2(f0.x, f1.x);
        *(float2*)(buf + SWZ((((c0 + 0) * 2 + dB) * 10 + sB) * 2)) = make_float2(f0.y, f1.y);
        *(float2*)(buf + SWZ((((c0 + 1) * 2 + dA) * 10 + sA) * 2)) = make_float2(f2.x, f3.x);
        *(float2*)(buf + SWZ((((c0 + 1) * 2 + dB) * 10 + sB) * 2)) = make_float2(f2.y, f3.y);
    }
}

// Qout == 1: four c's (4t..4t+3); per c the two p-bits are adjacent (float2)
__device__ __forceinline__ void sweep_step1(float* buf,
                                            const float* __restrict__ M,
                                            int t)
{
    const int c0 = 4 * t;
    uint64_t acc[4][10];
#pragma unroll
    for (int u = 0; u < 4; u++)
#pragma unroll
        for (int b2 = 0; b2 < 10; b2++) acc[u][b2] = 0ull;

#pragma unroll
    for (int rr = 0; rr < 10; rr++) {
        float2 v0 = *(const float2*)(buf + SWZ(((c0 + 0) * 10 + rr) * 2));
        float2 v1 = *(const float2*)(buf + SWZ(((c0 + 1) * 10 + rr) * 2));
        float2 v2 = *(const float2*)(buf + SWZ(((c0 + 2) * 10 + rr) * 2));
        float2 v3 = *(const float2*)(buf + SWZ(((c0 + 3) * 10 + rr) * 2));
        const uint64_t* M20 = (const uint64_t*)(M + (rr * 2 + 0) * 20);
        const uint64_t* M21 = (const uint64_t*)(M + (rr * 2 + 1) * 20);
        SWEEP_FMA_CORE(M20, v0.x, v1.x, v2.x, v3.x);
        SWEEP_FMA_CORE(M21, v0.y, v1.y, v2.y, v3.y);
    }

#pragma unroll
    for (int b2 = 0; b2 < 10; b2++) {
        const int bbA = 2 * b2, bbB = 2 * b2 + 1;
        const int dA = bbA / 10, sA = bbA % 10;
        const int dB = bbB / 10, sB = bbB % 10;
#pragma unroll
        for (int u = 0; u < 4; u++) {
            float2 f = u2f2(acc[u][b2]);
            buf[SWZ(((c0 + u) * 2 + dA) * 10 + sA)] = f.x;
            buf[SWZ(((c0 + u) * 2 + dB) * 10 + sB)] = f.y;
        }
    }
}

// ========================= Kernel 1: input sweep (in-place+SWZ, 128 thr, 57KB) =========================
__global__ __launch_bounds__(128, 4) void input_sweep_kernel(const float* __restrict__ x,
                                                             const float* __restrict__ ic)
{
    extern __shared__ float sm[];
    float* Mc  = sm;            // 4000 (16B aligned)
    float* buf = sm + 4000;     // 10240
    const int tid = threadIdx.x;    // 0..127
    const int bl = blockIdx.x;
    const int b = bl / 10, l = bl % 10;

    for (int t = tid; t < 4000; t += 128) Mc[t] = ic[t];
    __syncthreads();

    const float* xrow = x + b * 1024;
    for (int idx = tid; idx < 10240; idx += 128) {
        int q  = idx & 511;
        int cs = idx >> 9;
        int c = cs / 10, s = cs % 10;
        float w0 = Mc[((l * 2 + 0) * 2 + c) * 10 + s];
        float w1 = Mc[((l * 2 + 1) * 2 + c) * 10 + s];
        buf[SWZ(idx)] = xrow[q] * w0 + xrow[512 + q] * w1;
    }

    for (int i = 1; i <= 7; i++) {
        __syncthreads();
        sweep_step4(buf, Mc + i * 400, 512 >> i, 9 - i, tid);
    }
    __syncthreads();
    sweep_step2(buf, Mc + 8 * 400, tid);
    __syncthreads();
    sweep_step1(buf, Mc + 9 * 400, tid);
    __syncthreads();

    // final: buf[c*10 + r] -> fp16 rows of g_A
    const size_t rowbase = (size_t)bl * 10;
    for (int idx = tid; idx < 5120; idx += 128) {
        int rr = idx / 512, cp2 = idx % 512;
        int c0 = cp2 * 2;
        float va = buf[SWZ(c0 * 10 + rr)];
        float vb = buf[SWZ((c0 + 1) * 10 + rr)];
        __half2 h; h.x = __float2half(va); h.y = __float2half(vb);
        *(__half2*)&g_A[(rowbase + rr) * 1024 + c0] = h;
    }
}

// ========================= Kernel 2: B transpose (fp16) =========================
__global__ __launch_bounds__(256) void bconv_kernel(const float* __restrict__ cc)
{
    __shared__ float t[32][33];
    const int tx = threadIdx.x, ty = threadIdx.y;   // (32, 8)
    const int c0 = blockIdx.x * 32, d0 = blockIdx.y * 32;
#pragma unroll
    for (int i = 0; i < 32; i += 8)
        t[ty + i][tx] = cc[(size_t)(c0 + ty + i) * 1024 + d0 + tx];
    __syncthreads();
#pragma unroll
    for (int i = 0; i < 32; i += 8) {
        int d = ty + i;
        float v = t[tx][d];   // central[c0+tx][d0+d]
        g_Bt[(size_t)(d0 + d) * 1024 + c0 + tx] = __float2half(v);
    }
}

// ========================= Kernel 3: HMMA GEMM v5 — single-pass fp16 =========================
// U(51200x1024) = A @ Bh^T, K = 1024.
// CTA tile 128x128; 4 warps (2x2), warp tile 64x64; K-chunks of 64; 3 stages x 32KB -> 2 CTAs/SM.
#define G_STAGES 3
#define G_ABYTES 16384            // 128 rows x 128B (64 fp16)
#define G_BBYTES 16384
#define G_STAGE_BYTES (G_ABYTES + G_BBYTES)
#define G_NCHUNKS 16              // 1024 / 64

__device__ __forceinline__ void gemm_load_chunk(int kc, int stage, int m0, int n0,
                                                uint32_t smem_base, int tid)
{
    const int col = kc * 64;
    const uint32_t abase = smem_base + stage * G_STAGE_BYTES;
    const uint32_t bbase = abase + G_ABYTES;
#pragma unroll
    for (int i = 0; i < 8; i++) {                 // A: 1024 x 16B
        int idx = tid + i * 128;
        int r = idx >> 3, c = idx & 7;
        uint32_t dst = abase + (uint32_t)(r * 128 + ((c ^ (r & 7)) << 4));
        const void* src = (const void*)(g_A + (size_t)(m0 + r) * 1024 + col + c * 8);
        CP_ASYNC16(dst, src);
    }
#pragma unroll
    for (int i = 0; i < 8; i++) {                 // B: 1024 x 16B
        int idx = tid + i * 128;
        int r = idx >> 3, c = idx & 7;
        uint32_t dst = bbase + (uint32_t)(r * 128 + ((c ^ (r & 7)) << 4));
        const void* src = (const void*)(g_Bt + (size_t)(n0 + r) * 1024 + col + c * 8);
        CP_ASYNC16(dst, src);
    }
}

__global__ __launch_bounds__(128, 2) void gemm_mma_kernel()
{
    extern __shared__ char smc[];
    const uint32_t smem_base = smem_to_u32(smc);
    const int tid  = threadIdx.x;
    const int wid  = tid >> 5;      // 0..3
    const int lane = tid & 31;
    const int m0 = blockIdx.y * 128;
    const int n0 = blockIdx.x * 128;
    const int wm = (wid & 1) * 64;      // warp row in tile
    const int wn = (wid >> 1) * 64;     // warp col in tile

    float acc[4][8][4];
#pragma unroll
    for (int i = 0; i < 4; i++)
#pragma unroll
        for (int j = 0; j < 8; j++)
#pragma unroll
            for (int k = 0; k < 4; k++) acc[i][j][k] = 0.f;

    // prologue: chunks 0,1 into stages 0,1
#pragma unroll
    for (int c = 0; c < 2; c++) { gemm_load_chunk(c, c, m0, n0, smem_base, tid); CP_COMMIT(); }

    const int matA = lane >> 3;
    const int rowA_lo = (lane & 7) + ((matA & 1) << 3);
    const int kselA = matA >> 1;
    const int matB = lane >> 3;
    const int rowB_lo = (lane & 7) + ((matB >> 1) << 3);
    const int kselB = matB & 1;

    int stage = 0, lstage = 2;
    for (int kc = 0; kc < G_NCHUNKS; kc++) {
        CP_WAIT(1);
        __syncthreads();
        int pre = kc + 2; if (pre > G_NCHUNKS - 1) pre = G_NCHUNKS - 1;
        gemm_load_chunk(pre, lstage, m0, n0, smem_base, tid);
        CP_COMMIT();

        const uint32_t abase = smem_base + stage * G_STAGE_BYTES;
        const uint32_t bbase = abase + G_ABYTES;

#pragma unroll
        for (int kk = 0; kk < 4; kk++) {
            uint32_t af[4][4];
#pragma unroll
            for (int mt = 0; mt < 4; mt++) {
                int r = wm + mt * 16 + rowA_lo;
                int ch = 2 * kk + kselA;
                uint32_t addr = abase + (uint32_t)(r * 128 + ((ch ^ (r & 7)) << 4));
                LDMATRIX_X4(af[mt][0], af[mt][1], af[mt][2], af[mt][3], addr);
            }
            uint32_t bf[4][4];
#pragma unroll
            for (int p = 0; p < 4; p++) {
                int r = wn + p * 16 + rowB_lo;
                int ch = 2 * kk + kselB;
                uint32_t addr = bbase + (uint32_t)(r * 128 + ((ch ^ (r & 7)) << 4));
                LDMATRIX_X4(bf[p][0], bf[p][1], bf[p][2], bf[p][3], addr);
            }
#pragma unroll
            for (int mt = 0; mt < 4; mt++)
#pragma unroll
                for (int nt = 0; nt < 8; nt++) {
                    int p = nt >> 1, hi = nt & 1;
                    MMA_FP16(acc[mt][nt][0], acc[mt][nt][1], acc[mt][nt][2], acc[mt][nt][3],
                             af[mt][0], af[mt][1], af[mt][2], af[mt][3],
                             bf[p][2 * hi], bf[p][2 * hi + 1]);
                }
        }
        stage = (stage + 1 == 3) ? 0 : stage + 1;
        lstage = (lstage + 1 == 3) ? 0 : lstage + 1;
    }

    // epilogue
#pragma unroll
    for (int mt = 0; mt < 4; mt++) {
        int row = m0 + wm + mt * 16 + (lane >> 2);
#pragma unroll
        for (int nt = 0; nt < 8; nt++) {
            int col = n0 + wn + nt * 8 + (lane & 3) * 2;
            *(float2*)&g_U[(size_t)row * 1024 + col]       = make_float2(acc[mt][nt][0], acc[mt][nt][1]);
            *(float2*)&g_U[(size_t)(row + 8) * 1024 + col] = make_float2(acc[mt][nt][2], acc[mt][nt][3]);
        }
    }
}

// ========================= Kernel 4: output sweep (in-place+SWZ, 128 thr, 57KB) =========================
__global__ __launch_bounds__(128, 4) void output_sweep_kernel(const float* __restrict__ oc)
{
    extern __shared__ float sm[];
    float* Mc  = sm;            // 4000 (permuted)
    float* buf = sm + 4000;     // 10240
    const int tid = threadIdx.x;    // 0..127
    const int bl = blockIdx.x;
    const int l = bl % 10;
    const size_t rowbase = (size_t)bl * 10;

    for (int t = tid; t < 4000; t += 128) {
        int j = t / 400, rem = t % 400;
        int a = rem / 20, bc = rem % 20;
        int rr = a >> 1, d = a & 1, p = bc / 10, s = bc % 10;
        Mc[t] = oc[j * 400 + rr * 40 + p * 20 + d * 10 + s];
    }
    for (int idx = tid; idx < 10240; idx += 128)
        buf[SWZ(idx)] = g_U[rowbase * 1024 + idx];
    __syncthreads();

    for (int j = 0; j <= 7; j++) {
        sweep_step4(buf, Mc + j * 400, 512 >> j, 9 - j, tid);
        __syncthreads();
    }
    sweep_step2(buf, Mc + 8 * 400, tid);
    __syncthreads();
    sweep_step1(buf, Mc + 9 * 400, tid);
    __syncthreads();

    for (int p = tid; p < 1024; p += 128)
        g_P[(size_t)bl * 1024 + p] = buf[SWZ(p * 10 + l)];
}

// ========================= Kernel 5: reduce =========================
__global__ __launch_bounds__(256) void reduce_kernel(const float* __restrict__ bias,
                                                     float* __restrict__ out)
{
    const int b = blockIdx.x;
    for (int p = threadIdx.x; p < 1024; p += 256) {
        float s = bias[p];
#pragma unroll
        for (int l = 0; l < 10; l++) s += g_P[(size_t)(b * 10 + l) * 1024 + p];
        out[b * 1024 + p] = s;
    }
}

// ========================= launch =========================
extern "C" void kernel_launch(void* const* d_in, const int* in_sizes, int n_in,
                              void* d_out, int out_size)
{
    (void)in_sizes; (void)n_in; (void)out_size;
    const float* x    = (const float*)d_in[0];
    const float* ic   = (const float*)d_in[1];
    const float* oc   = (const float*)d_in[2];
    const float* cc   = (const float*)d_in[3];
    const float* bias = (const float*)d_in[4];
    float* out = (float*)d_out;

    const int SMEM_SWEEP = (4000 + 10240) * 4;              // 56960 B -> 4 CTAs/SM
    const int SMEM_GEMM  = G_STAGES * G_STAGE_BYTES;        // 98304 B -> 2 CTAs/SM
    cudaFuncSetAttribute(input_sweep_kernel,  cudaFuncAttributeMaxDynamicSharedMemorySize, SMEM_SWEEP);
    cudaFuncSetAttribute(output_sweep_kernel, cudaFuncAttributeMaxDynamicSharedMemorySize, SMEM_SWEEP);
    cudaFuncSetAttribute(gemm_mma_kernel,     cudaFuncAttributeMaxDynamicSharedMemorySize, SMEM_GEMM);

    input_sweep_kernel<<<5120, 128, SMEM_SWEEP>>>(x, ic);
    bconv_kernel<<<dim3(32, 32), dim3(32, 8)>>>(cc);
    gemm_mma_kernel<<<dim3(8, 400), 128, SMEM_GEMM>>>();
    output_sweep_kernel<<<5120, 128, SMEM_SWEEP>>>(oc);
    reduce_kernel<<<512, 256>>>(bias, out);
}